// round 14
// baseline (speedup 1.0000x reference)
#include <cuda_runtime.h>
#include <cuda_fp16.h>
#include <math.h>
#include <stdint.h>

#define CIN   64
#define COUT  128
#define HH    128
#define WW    128
#define NB    32

// ---------------- persistent scratch (__device__ globals) -------------------
__device__ uint4 g_x1[(size_t)NB * HH * 1024];   // [n][h][pix(128)][ic(64)] fp16
__device__ uint4 g_u[16 * 1024];                 // [pos][oc(128)][ic(64)] fp16

// ---------------- pre-pass: x -> fp16 transposed tiles ----------------------
__global__ void prep_x(const float* __restrict__ x) {
    __shared__ __half sh[128 * 72];
    const int h = blockIdx.x, n = blockIdx.y;
    const float* xb = x + (size_t)n * CIN * HH * WW;
#pragma unroll
    for (int i = 0; i < 8; i++) {
        int f = threadIdx.x + i * 256;
        int ic = f >> 5, p4 = f & 31;
        float4 v = *(const float4*)(xb + ((size_t)ic * HH + h) * WW + p4 * 4);
        float vv[4] = {v.x, v.y, v.z, v.w};
#pragma unroll
        for (int j = 0; j < 4; j++)
            sh[(p4 * 4 + j) * 72 + ic] = __float2half_rn(vv[j]);
    }
    __syncthreads();
    uint4* dst = g_x1 + (size_t)(n * HH + h) * 1024;
    for (int q = threadIdx.x; q < 1024; q += 256) {
        int p = q >> 3, c = q & 7;
        dst[q] = *(const uint4*)((const char*)sh + p * 144 + c * 16);
    }
}

// ---------------- pre-pass: weights -> Winograd U (fp32-exact -> fp16) ------
__global__ void prep_uw(const float* __restrict__ w) {
    int idx = blockIdx.x * 256 + threadIdx.x;
    if (idx >= COUT * CIN) return;
    int oc = idx >> 6, ic = idx & 63;
    float g[3][3];
#pragma unroll
    for (int r = 0; r < 3; r++)
#pragma unroll
        for (int c = 0; c < 3; c++)
            g[r][c] = w[((size_t)(ic * COUT + oc) * 3 + (2 - r)) * 3 + (2 - c)];
    float t[4][3];
#pragma unroll
    for (int c = 0; c < 3; c++) {
        t[0][c] = g[0][c];
        t[1][c] = 0.5f * (g[0][c] + g[1][c] + g[2][c]);
        t[2][c] = 0.5f * (g[0][c] - g[1][c] + g[2][c]);
        t[3][c] = g[2][c];
    }
    __half* dst = (__half*)g_u;
#pragma unroll
    for (int r = 0; r < 4; r++) {
        float u0 = t[r][0];
        float u1 = 0.5f * (t[r][0] + t[r][1] + t[r][2]);
        float u2 = 0.5f * (t[r][0] - t[r][1] + t[r][2]);
        float u3 = t[r][2];
        dst[((r * 4 + 0) * COUT + oc) * 64 + ic] = __float2half_rn(u0);
        dst[((r * 4 + 1) * COUT + oc) * 64 + ic] = __float2half_rn(u1);
        dst[((r * 4 + 2) * COUT + oc) * 64 + ic] = __float2half_rn(u2);
        dst[((r * 4 + 3) * COUT + oc) * 64 + ic] = __float2half_rn(u3);
    }
}

// ---------------- main kernel ----------------------------------------------
// CTA = 512 thr, output rows {2hb,2hb+1} x 128 px (64 tiles). 1 CTA/SM.
// smem: V [16 pos][64 tiles][128B swz]          = 131072  @ 0
//       U 4 bufs [128 oc][128B swz]             =  65536  @ 131072
//       X 2 bufs [4 rows][132 lp][32B] (quarter)=  33792  @ 196608
#define VPOS_B 8192
#define US     131072
#define UT_B   16384
#define XS     196608
#define XQ_B   16896
#define SMEM_SZ 230400

static __device__ __forceinline__ unsigned smem_u32(const void* p) {
    unsigned r;
    asm("{ .reg .u64 t; cvta.to.shared.u64 t, %1; cvt.u32.u64 %0, t; }"
        : "=r"(r) : "l"(p));
    return r;
}
__device__ __forceinline__ void cp16(unsigned dst, const void* src, int bytes) {
    asm volatile("cp.async.cg.shared.global [%0], [%1], 16, %2;"
                 :: "r"(dst), "l"(src), "r"(bytes));
}
__device__ __forceinline__ void cp_commit() {
    asm volatile("cp.async.commit_group;");
}
__device__ __forceinline__ void ldsm4(unsigned r[4], unsigned addr) {
    asm volatile("ldmatrix.sync.aligned.m8n8.x4.shared.b16 {%0,%1,%2,%3}, [%4];"
                 : "=r"(r[0]), "=r"(r[1]), "=r"(r[2]), "=r"(r[3]) : "r"(addr));
}
__device__ __forceinline__ void mma16816(float c[4], const unsigned a[4],
                                         unsigned b0, unsigned b1) {
    asm volatile(
        "mma.sync.aligned.m16n8k16.row.col.f32.f16.f16.f32 "
        "{%0,%1,%2,%3}, {%4,%5,%6,%7}, {%8,%9}, {%0,%1,%2,%3};"
        : "+f"(c[0]), "+f"(c[1]), "+f"(c[2]), "+f"(c[3])
        : "r"(a[0]), "r"(a[1]), "r"(a[2]), "r"(a[3]), "r"(b0), "r"(b1));
}
__device__ __forceinline__ float gelu_tanh(float y) {
    float u = 1.5957691216f * (y + 0.044715f * y * y * y);
    return __fdividef(y, 1.0f + __expf(-u));
}

extern __shared__ char dyn_smem[];

__global__ __launch_bounds__(512, 1)
void convt_wino_kernel(const float* __restrict__ bias,
                       const float* __restrict__ gnw,
                       const float* __restrict__ gnb,
                       float* __restrict__ out) {
    const int hb = blockIdx.x;          // output rows {2hb, 2hb+1}
    const int n = blockIdx.y;
    const int tid = threadIdx.x;
    const int wid = tid >> 5;
    const int l = tid & 31;
    const int wm = wid >> 2;            // 0..3 -> oc base wm*32
    const int wn = wid & 3;             // 0..3 -> tile base wn*16
    const int bar_id = wm + 1;

    const unsigned sb = smem_u32(dyn_smem);

    // ---- U slice loader: wm-group leader warp (wn==0) loads oc rows
    //      [wm*32, wm*32+32); lane l -> row wm*32+l, 8x16B swizzled.
    //      Non-leaders commit EMPTY groups to keep per-thread group counts
    //      uniform.
    auto issue_u = [&](int pos, int buf) {
        if (wn == 0) {
            int row = wm * 32 + l;
            unsigned drow = sb + US + (unsigned)buf * UT_B + (unsigned)row * 128;
            const char* srow = (const char*)g_u + (size_t)pos * 16384 + row * 128;
            const unsigned xr = (unsigned)((l & 7) << 4);
#pragma unroll
            for (int k = 0; k < 8; k++)
                cp16(drow + (((unsigned)(k * 16)) ^ xr), srow + k * 16, 16);
        }
        cp_commit();
    };
    // ---- x quarter load: ic quarter hf (16 ic = 32B) into x buf xb ----
    auto issue_x = [&](int hf, int xb) {
#pragma unroll
        for (int k = 0; k < 3; k++) {
            int idx = tid + k * 512;            // need < 1056
            if (idx < 4 * 132 * 2) {
                int c = idx & 1;
                int lp = (idx >> 1) % 132;
                int i = idx / (132 * 2);
                int gh = 2 * hb - 2 + i;
                int gp = lp - 2;
                bool ok = (gh >= 0) && (gp >= 0) && (gp < WW);
                const char* src = (const char*)g_x1 +
                    (size_t)(n * HH + (gh < 0 ? 0 : gh)) * 16384 +
                    (ok ? gp : 0) * 128 + hf * 32 + c * 16;
                cp16(sb + XS + (unsigned)xb * XQ_B +
                     (unsigned)(i * 132 + lp) * 32 + c * 16, src, ok ? 16 : 0);
            }
        }
        cp_commit();
    };

    // ---- prologue: U0-2 + x0,x1 upfront, then 4 pipelined transform phases --
    issue_u(0, 0);              // g1
    issue_u(1, 1);              // g2
    issue_u(2, 2);              // g3
    issue_x(0, 0);              // g4
    issue_x(1, 1);              // g5

#pragma unroll
    for (int hf = 0; hf < 4; hf++) {
        if (hf < 3) asm volatile("cp.async.wait_group 1;");
        else        asm volatile("cp.async.wait_group 0;");
        __syncthreads();                      // x quarter hf visible CTA-wide

        // transform: unit = (tile tl, ic-pair q within quarter), 1/thread
        {
            const int tl = tid >> 3, q = tid & 7;
            const unsigned xbase = sb + XS + (unsigned)(hf & 1) * XQ_B;
            const unsigned vxr = (unsigned)((tl & 7) << 4);
            const unsigned vcol = (unsigned)(((hf * 8 + q) * 4)) ^ vxr;
            float2 d[4][4];
#pragma unroll
            for (int i = 0; i < 4; i++)
#pragma unroll
                for (int jj = 0; jj < 4; jj++) {
                    __half2 hv = *(const __half2*)
                        (dyn_smem + (xbase - sb) + (i * 132 + 2 * tl + jj) * 32 + q * 4);
                    d[i][jj] = __half22float2(hv);
                }
            float2 e[4][4];
#pragma unroll
            for (int jj = 0; jj < 4; jj++) {
                e[0][jj] = make_float2(d[0][jj].x - d[2][jj].x, d[0][jj].y - d[2][jj].y);
                e[1][jj] = make_float2(d[1][jj].x + d[2][jj].x, d[1][jj].y + d[2][jj].y);
                e[2][jj] = make_float2(d[2][jj].x - d[1][jj].x, d[2][jj].y - d[1][jj].y);
                e[3][jj] = make_float2(d[1][jj].x - d[3][jj].x, d[1][jj].y - d[3][jj].y);
            }
#pragma unroll
            for (int r = 0; r < 4; r++) {
                float2 v[4];
                v[0] = make_float2(e[r][0].x - e[r][2].x, e[r][0].y - e[r][2].y);
                v[1] = make_float2(e[r][1].x + e[r][2].x, e[r][1].y + e[r][2].y);
                v[2] = make_float2(e[r][2].x - e[r][1].x, e[r][2].y - e[r][1].y);
                v[3] = make_float2(e[r][1].x - e[r][3].x, e[r][1].y - e[r][3].y);
#pragma unroll
                for (int s = 0; s < 4; s++)
                    *(__half2*)(dyn_smem + (r * 4 + s) * VPOS_B + tl * 128 + vcol) =
                        __floats2half2_rn(v[s].x, v[s].y);
            }
        }
        __syncthreads();                      // transform hf reads done
        if (hf < 2) issue_x(hf + 2, hf & 1);  // refill the buffer just freed
    }
    // V complete; U0-2 resident. No CTA-wide barriers from here on.

    // ---- per-lane ldsm components ----
    const unsigned aBase = (unsigned)(wm * 32 + (l & 15)) * 128;
    const unsigned aColB = (unsigned)((l >> 4) * 16);
    const unsigned aXr = (unsigned)((l & 7) << 4);
    const int bRow = (l & 7) + ((l & 16) ? 8 : 0);
    const unsigned bXr = (unsigned)((bRow & 7) << 4);
    const unsigned bKoff = (l & 8) ? 16u : 0u;
    const unsigned vRowB = (unsigned)(wn * 16 + bRow) * 128;

    float Y[2][2][4][4];
#pragma unroll
    for (int tm = 0; tm < 2; tm++)
#pragma unroll
        for (int tn = 0; tn < 2; tn++)
#pragma unroll
            for (int c = 0; c < 4; c++)
#pragma unroll
                for (int ab = 0; ab < 4; ab++) Y[tm][tn][c][ab] = 0.f;

    constexpr float AR[2][4] = {{1.f, 1.f, 1.f, 0.f}, {0.f, 1.f, -1.f, -1.f}};

    // ---- mainloop: 16 positions, 4-buf U, per-wm-group named barriers ------
#pragma unroll
    for (int p = 0; p < 16; p++) {
        asm volatile("cp.async.wait_group 2;");       // leader: U[p] landed
        asm volatile("bar.sync %0, 128;" :: "r"(bar_id) : "memory");
        // all 4 warps of this wm-group past pos p-1 reads; U[p] visible

        if (p + 3 < 16) issue_u(p + 3, (p + 3) & 3);  // overwrites U[p-1] buf
        else cp_commit();

        const int pr = p >> 2, pc = p & 3;
        const unsigned ub = sb + US + (unsigned)(p & 3) * UT_B + aBase;
        const unsigned vb = sb + (unsigned)p * VPOS_B + vRowB;

        float tmp[2][2][4];
#pragma unroll
        for (int tm = 0; tm < 2; tm++)
#pragma unroll
            for (int tn = 0; tn < 2; tn++)
#pragma unroll
                for (int c = 0; c < 4; c++) tmp[tm][tn][c] = 0.f;

#pragma unroll
        for (int kc = 0; kc < 4; kc++) {
            unsigned a0[4], a1[4], bf[4];
            const unsigned acs = ((unsigned)(kc * 32) + aColB) ^ aXr;
            ldsm4(a0, ub + acs);
            ldsm4(a1, ub + 2048 + acs);
            ldsm4(bf, vb + (((unsigned)(kc * 32) + bKoff) ^ bXr));
            mma16816(tmp[0][0], a0, bf[0], bf[1]);
            mma16816(tmp[0][1], a0, bf[2], bf[3]);
            mma16816(tmp[1][0], a1, bf[0], bf[1]);
            mma16816(tmp[1][1], a1, bf[2], bf[3]);
        }

        // fold inverse transform (coefs 0/+-1, compile-time)
#pragma unroll
        for (int tm = 0; tm < 2; tm++)
#pragma unroll
            for (int tn = 0; tn < 2; tn++)
#pragma unroll
                for (int c = 0; c < 4; c++) {
                    float m = tmp[tm][tn][c];
#pragma unroll
                    for (int a = 0; a < 2; a++) {
                        if (AR[a][pr] == 0.f) continue;
#pragma unroll
                        for (int b = 0; b < 2; b++) {
                            if (AR[b][pc] == 0.f) continue;
                            Y[tm][tn][c][a * 2 + b] += AR[a][pr] * AR[b][pc] * m;
                        }
                    }
                }
    }

    // ---------------- epilogue: bias + GELU + per-pixel GN + store ----------
    const int ocr = wm * 32 + (l >> 2);                 // tm adds +16
#pragma unroll
    for (int tm = 0; tm < 2; tm++) {
        const int r0 = ocr + tm * 16;
        const float b_lo = __ldg(bias + r0), b_hi = __ldg(bias + r0 + 8);
        const float w_lo = __ldg(gnw + r0),  w_hi = __ldg(gnw + r0 + 8);
        const float a_lo = __ldg(gnb + r0),  a_hi = __ldg(gnb + r0 + 8);
#pragma unroll
        for (int tn = 0; tn < 2; tn++) {
            float g[4][4], o[4][4];
#pragma unroll
            for (int ab = 0; ab < 4; ab++) {
                g[0][ab] = gelu_tanh(Y[tm][tn][0][ab] + b_lo);
                g[1][ab] = gelu_tanh(Y[tm][tn][1][ab] + b_lo);
                g[2][ab] = gelu_tanh(Y[tm][tn][2][ab] + b_hi);
                g[3][ab] = gelu_tanh(Y[tm][tn][3][ab] + b_hi);
            }
#pragma unroll
            for (int u = 0; u < 2; u++)
#pragma unroll
                for (int ab = 0; ab < 4; ab++) {
                    float v0 = g[u][ab], v1 = g[u + 2][ab];
                    float s1 = v0 + v1, s2 = v0 * v0 + v1 * v1;
#pragma unroll
                    for (int m = 4; m <= 16; m <<= 1) {
                        s1 += __shfl_xor_sync(0xffffffffu, s1, m);
                        s2 += __shfl_xor_sync(0xffffffffu, s2, m);
                    }
                    float mean = s1 * (1.0f / 16.0f);
                    float var  = s2 * (1.0f / 16.0f) - mean * mean;
                    float rstd = rsqrtf(var + 1e-5f);
                    o[u][ab]     = (v0 - mean) * rstd * w_lo + a_lo;
                    o[u + 2][ab] = (v1 - mean) * rstd * w_hi + a_hi;
                }
            int colbase = wn * 32 + 16 * tn + 4 * (l & 3);
#pragma unroll
            for (int rr = 0; rr < 2; rr++) {
                int oc = r0 + rr * 8;
#pragma unroll
                for (int a = 0; a < 2; a++) {
                    float* dst = out + (((size_t)n * COUT + oc) * HH +
                                        (2 * hb + a)) * WW + colbase;
                    *(float4*)dst = make_float4(o[rr * 2 + 0][a * 2 + 0],
                                                o[rr * 2 + 0][a * 2 + 1],
                                                o[rr * 2 + 1][a * 2 + 0],
                                                o[rr * 2 + 1][a * 2 + 1]);
                }
            }
        }
    }
}

extern "C" void kernel_launch(void* const* d_in, const int* in_sizes, int n_in,
                              void* d_out, int out_size) {
    const float* x   = (const float*)d_in[0];
    const float* w   = (const float*)d_in[1];
    const float* b   = (const float*)d_in[2];
    const float* gnw = (const float*)d_in[3];
    const float* gnb = (const float*)d_in[4];
    float* out = (float*)d_out;

    prep_uw<<<32, 256>>>(w);
    prep_x<<<dim3(HH, NB), 256>>>(x);

    cudaFuncSetAttribute(convt_wino_kernel,
                         cudaFuncAttributeMaxDynamicSharedMemorySize, SMEM_SZ);
    convt_wino_kernel<<<dim3(HH / 2, NB), 512, SMEM_SZ>>>(b, gnw, gnb, out);
}

// round 15
// speedup vs baseline: 1.4352x; 1.4352x over previous
#include <cuda_runtime.h>
#include <cuda_fp16.h>
#include <math.h>
#include <stdint.h>

#define CIN   64
#define COUT  128
#define HH    128
#define WW    128
#define NB    32

// ---------------- persistent scratch (__device__ globals) -------------------
__device__ uint4 g_x1[(size_t)NB * HH * 1024];   // [n][h][pix(128)][ic(64)] fp16
__device__ uint4 g_u[16 * 1024];                 // [pos][oc(128)][ic(64)] fp16
                                                 // (corner pos 3,12 sign-folded)

// ---------------- fused pre-pass: blocks 0..31 = U, 32..4127 = x ------------
__global__ void prep_all(const float* __restrict__ w,
                         const float* __restrict__ x) {
    __shared__ __half sh[128 * 72];
    const int bid = blockIdx.x;

    if (bid < 32) {
        // ---- Winograd U (fp32-exact -> fp16), signs folded for corners ----
        int idx = bid * 256 + threadIdx.x;          // 0..8191 = oc*64+ic
        if (idx >= COUT * CIN) return;
        int oc = idx >> 6, ic = idx & 63;
        float g[3][3];
#pragma unroll
        for (int r = 0; r < 3; r++)
#pragma unroll
            for (int c = 0; c < 3; c++)
                g[r][c] = w[((size_t)(ic * COUT + oc) * 3 + (2 - r)) * 3 + (2 - c)];
        float t[4][3];
#pragma unroll
        for (int c = 0; c < 3; c++) {
            t[0][c] = g[0][c];
            t[1][c] = 0.5f * (g[0][c] + g[1][c] + g[2][c]);
            t[2][c] = 0.5f * (g[0][c] - g[1][c] + g[2][c]);
            t[3][c] = g[2][c];
        }
        __half* dst = (__half*)g_u;
#pragma unroll
        for (int r = 0; r < 4; r++) {
            float u0 = t[r][0];
            float u1 = 0.5f * (t[r][0] + t[r][1] + t[r][2]);
            float u2 = 0.5f * (t[r][0] - t[r][1] + t[r][2]);
            float u3 = t[r][2];
            if (r == 3) u0 = -u0;       // pos 12 = (3,0): a-coef -1
            if (r == 0) u3 = -u3;       // pos 3  = (0,3): b-coef -1
            dst[((r * 4 + 0) * COUT + oc) * 64 + ic] = __float2half_rn(u0);
            dst[((r * 4 + 1) * COUT + oc) * 64 + ic] = __float2half_rn(u1);
            dst[((r * 4 + 2) * COUT + oc) * 64 + ic] = __float2half_rn(u2);
            dst[((r * 4 + 3) * COUT + oc) * 64 + ic] = __float2half_rn(u3);
        }
        return;
    }

    // ---- x -> fp16 transposed tiles ----
    const int r2 = bid - 32;
    const int h = r2 & 127, n = r2 >> 7;
    const float* xb = x + (size_t)n * CIN * HH * WW;
#pragma unroll
    for (int i = 0; i < 8; i++) {
        int f = threadIdx.x + i * 256;
        int ic = f >> 5, p4 = f & 31;
        float4 v = *(const float4*)(xb + ((size_t)ic * HH + h) * WW + p4 * 4);
        float vv[4] = {v.x, v.y, v.z, v.w};
#pragma unroll
        for (int j = 0; j < 4; j++)
            sh[(p4 * 4 + j) * 72 + ic] = __float2half_rn(vv[j]);
    }
    __syncthreads();
    uint4* dst = g_x1 + (size_t)(n * HH + h) * 1024;
    for (int q = threadIdx.x; q < 1024; q += 256) {
        int p = q >> 3, c = q & 7;
        dst[q] = *(const uint4*)((const char*)sh + p * 144 + c * 16);
    }
}

// ---------------- main kernel ----------------------------------------------
// CTA = output rows {2hb, 2hb+1} x 64 pixels (32 Winograd tiles).
// smem (XOR-swizzled 128B rows):
//   V  [16 pos][32 tiles][128B]          = 65536
//   U  3 bufs  [128 oc][128B]            = 49152  (x stage 34816B aliased)
#define VPOS_B 4096
#define US     65536
#define UT_B   16384
#define SMEM_SZ 114688

static __device__ __forceinline__ unsigned smem_u32(const void* p) {
    unsigned r;
    asm("{ .reg .u64 t; cvta.to.shared.u64 t, %1; cvt.u32.u64 %0, t; }"
        : "=r"(r) : "l"(p));
    return r;
}
__device__ __forceinline__ void cp16(unsigned dst, const void* src, int bytes) {
    asm volatile("cp.async.cg.shared.global [%0], [%1], 16, %2;"
                 :: "r"(dst), "l"(src), "r"(bytes));
}
__device__ __forceinline__ void cp_commit() {
    asm volatile("cp.async.commit_group;");
}
__device__ __forceinline__ void ldsm4(unsigned r[4], unsigned addr) {
    asm volatile("ldmatrix.sync.aligned.m8n8.x4.shared.b16 {%0,%1,%2,%3}, [%4];"
                 : "=r"(r[0]), "=r"(r[1]), "=r"(r[2]), "=r"(r[3]) : "r"(addr));
}
// accumulate: d == c
__device__ __forceinline__ void mma16816(float c[4], const unsigned a[4],
                                         unsigned b0, unsigned b1) {
    asm volatile(
        "mma.sync.aligned.m16n8k16.row.col.f32.f16.f16.f32 "
        "{%0,%1,%2,%3}, {%4,%5,%6,%7}, {%8,%9}, {%0,%1,%2,%3};"
        : "+f"(c[0]), "+f"(c[1]), "+f"(c[2]), "+f"(c[3])
        : "r"(a[0]), "r"(a[1]), "r"(a[2]), "r"(a[3]), "r"(b0), "r"(b1));
}
// separate d and c (used with c = zeros to skip tmp zeroing)
__device__ __forceinline__ void mma16816_dc(float d[4], const unsigned a[4],
                                            unsigned b0, unsigned b1,
                                            const float c[4]) {
    asm volatile(
        "mma.sync.aligned.m16n8k16.row.col.f32.f16.f16.f32 "
        "{%0,%1,%2,%3}, {%4,%5,%6,%7}, {%8,%9}, {%10,%11,%12,%13};"
        : "=f"(d[0]), "=f"(d[1]), "=f"(d[2]), "=f"(d[3])
        : "r"(a[0]), "r"(a[1]), "r"(a[2]), "r"(a[3]), "r"(b0), "r"(b1),
          "f"(c[0]), "f"(c[1]), "f"(c[2]), "f"(c[3]));
}
__device__ __forceinline__ float gelu_tanh(float y) {
    float u = 1.5957691216f * (y + 0.044715f * y * y * y);
    return __fdividef(y, 1.0f + __expf(-u));
}

extern __shared__ char dyn_smem[];

__global__ __launch_bounds__(256, 2)
void convt_wino_kernel(const float* __restrict__ bias,
                       const float* __restrict__ gnw,
                       const float* __restrict__ gnb,
                       float* __restrict__ out) {
    const int hb = blockIdx.x >> 1;     // output rows {2hb, 2hb+1}
    const int ps = blockIdx.x & 1;      // pixel slice: 64 px at ps*64
    const int n = blockIdx.y;
    const int tid = threadIdx.x;
    const int wid = tid >> 5;
    const int l = tid & 31;

    const unsigned sb = smem_u32(dyn_smem);

    // ---- prologue: x stage (4 rows x 68 lp x 64 ic) into U region ----------
    {
#pragma unroll
        for (int k = 0; k < 9; k++) {
            int idx = tid + k * 256;            // need < 2176
            if (idx < 4 * 68 * 8) {
                int c = idx & 7;
                int lp = (idx >> 3) % 68;
                int i = idx / (68 * 8);
                int gh = 2 * hb - 2 + i;
                int gp = ps * 64 - 2 + lp;
                bool ok = (gh >= 0) && (gp >= 0) && (gp < WW);
                const char* src = (const char*)g_x1 +
                    (size_t)(n * HH + (gh < 0 ? 0 : gh)) * 16384 +
                    (ok ? gp : 0) * 128 + c * 16;
                cp16(sb + US + (unsigned)(i * 68 + lp) * 128 + c * 16, src,
                     ok ? 16 : 0);
            }
        }
        cp_commit();
        asm volatile("cp.async.wait_group 0;");
        __syncthreads();
    }

    // ---- V transform (fp32 math, fp16 store, swizzled rows) ----------------
#pragma unroll
    for (int jb = 0; jb < 4; jb++) {
        int idx = tid + jb * 256;       // 0..1023
        int tl = idx >> 5, q = idx & 31;
        const unsigned vxr = (unsigned)((tl & 7) << 4);
        float2 d[4][4];
#pragma unroll
        for (int i = 0; i < 4; i++)
#pragma unroll
            for (int jj = 0; jj < 4; jj++) {
                __half2 hv = *(const __half2*)
                    (dyn_smem + US + (i * 68 + 2 * tl + jj) * 128 + q * 4);
                d[i][jj] = __half22float2(hv);
            }
        float2 e[4][4];
#pragma unroll
        for (int jj = 0; jj < 4; jj++) {
            e[0][jj] = make_float2(d[0][jj].x - d[2][jj].x, d[0][jj].y - d[2][jj].y);
            e[1][jj] = make_float2(d[1][jj].x + d[2][jj].x, d[1][jj].y + d[2][jj].y);
            e[2][jj] = make_float2(d[2][jj].x - d[1][jj].x, d[2][jj].y - d[1][jj].y);
            e[3][jj] = make_float2(d[1][jj].x - d[3][jj].x, d[1][jj].y - d[3][jj].y);
        }
#pragma unroll
        for (int r = 0; r < 4; r++) {
            float2 v[4];
            v[0] = make_float2(e[r][0].x - e[r][2].x, e[r][0].y - e[r][2].y);
            v[1] = make_float2(e[r][1].x + e[r][2].x, e[r][1].y + e[r][2].y);
            v[2] = make_float2(e[r][2].x - e[r][1].x, e[r][2].y - e[r][1].y);
            v[3] = make_float2(e[r][1].x - e[r][3].x, e[r][1].y - e[r][3].y);
#pragma unroll
            for (int s = 0; s < 4; s++)
                *(__half2*)(dyn_smem + (r * 4 + s) * VPOS_B + tl * 128 +
                            (unsigned)((q * 4) ^ vxr)) =
                    __floats2half2_rn(v[s].x, v[s].y);
        }
    }
    __syncthreads();                    // LAST barrier in the kernel

    // ---- per-warp U slice load: warp w loads only oc rows [w*16, w*16+16) --
    const int ur = l & 15;
    const int uhf = l >> 4;
    const unsigned uxr = (unsigned)((ur & 7) << 4);
    auto issue_u = [&](int pos, int buf) {
        unsigned drow = sb + US + (unsigned)buf * UT_B +
                        (unsigned)(wid * 16 + ur) * 128;
        const char* srow = (const char*)g_u + (size_t)pos * 16384 +
                           (wid * 16 + ur) * 128 + uhf * 64;
#pragma unroll
        for (int k2 = 0; k2 < 4; k2++)
            cp16(drow + (((unsigned)(uhf * 64 + k2 * 16)) ^ uxr),
                 srow + k2 * 16, 16);
        cp_commit();
    };
    issue_u(0, 0);
    issue_u(1, 1);
    issue_u(2, 2);

    // ---- per-lane ldmatrix components ----
    const unsigned aBase = (unsigned)(wid * 16 + (l & 15)) * 128;
    const unsigned aColB = (unsigned)((l >> 4) * 16);
    const unsigned aXr = (unsigned)((l & 7) << 4);
    const int bRow = (l & 7) + ((l & 16) ? 8 : 0);
    const unsigned bXr = (unsigned)((bRow & 7) << 4);
    const unsigned bKoff = (l & 8) ? 16u : 0u;

    // ---- Y accumulators: [pi][tn][ab][c]  (ab-major so c-quad = mma group) --
    float Y[2][2][4][4];
#pragma unroll
    for (int pi = 0; pi < 2; pi++)
#pragma unroll
        for (int tn = 0; tn < 2; tn++)
#pragma unroll
            for (int ab = 0; ab < 4; ab++)
#pragma unroll
                for (int c = 0; c < 4; c++) Y[pi][tn][ab][c] = 0.f;

    float zero4[4] = {0.f, 0.f, 0.f, 0.f};
    constexpr float AR[2][4] = {{1.f, 1.f, 1.f, 0.f}, {0.f, 1.f, -1.f, -1.f}};

    // ---- barrier-free mainloop over 16 Winograd positions ------------------
#pragma unroll
    for (int p = 0; p < 16; p++) {
        asm volatile("cp.async.wait_group 2;");   // this warp's U[p] ready

        const int pr = p >> 2, pc = p & 3;
        const bool corner = (pr == 0 || pr == 3) && (pc == 0 || pc == 3);
        const int cab = (pr ? 2 : 0) + (pc ? 1 : 0);   // corner target slot
        const unsigned ub = sb + US + (unsigned)(p % 3) * UT_B + aBase;
        const unsigned vb0 = sb + (unsigned)p * VPOS_B + (unsigned)bRow * 128;
        const unsigned vb1 = vb0 + 2048;

        if (corner) {
            // signs folded into g_u at prep time: accumulate straight into Y
#pragma unroll
            for (int kc = 0; kc < 4; kc++) {
                unsigned af[4], b0[4], b1[4];
                ldsm4(af, ub + (((unsigned)(kc * 32) + aColB) ^ aXr));
                const unsigned csw = ((unsigned)(kc * 32) + bKoff) ^ bXr;
                ldsm4(b0, vb0 + csw);
                ldsm4(b1, vb1 + csw);
                mma16816(Y[0][0][cab], af, b0[0], b0[1]);
                mma16816(Y[0][1][cab], af, b0[2], b0[3]);
                mma16816(Y[1][0][cab], af, b1[0], b1[1]);
                mma16816(Y[1][1][cab], af, b1[2], b1[3]);
            }
        } else {
            float tmp[2][2][4];
#pragma unroll
            for (int kc = 0; kc < 4; kc++) {
                unsigned af[4], b0[4], b1[4];
                ldsm4(af, ub + (((unsigned)(kc * 32) + aColB) ^ aXr));
                const unsigned csw = ((unsigned)(kc * 32) + bKoff) ^ bXr;
                ldsm4(b0, vb0 + csw);
                ldsm4(b1, vb1 + csw);
                if (kc == 0) {
                    mma16816_dc(tmp[0][0], af, b0[0], b0[1], zero4);
                    mma16816_dc(tmp[0][1], af, b0[2], b0[3], zero4);
                    mma16816_dc(tmp[1][0], af, b1[0], b1[1], zero4);
                    mma16816_dc(tmp[1][1], af, b1[2], b1[3], zero4);
                } else {
                    mma16816(tmp[0][0], af, b0[0], b0[1]);
                    mma16816(tmp[0][1], af, b0[2], b0[3]);
                    mma16816(tmp[1][0], af, b1[0], b1[1]);
                    mma16816(tmp[1][1], af, b1[2], b1[3]);
                }
            }
            // fold inverse transform (coefs 0/+-1, compile-time pruned)
#pragma unroll
            for (int pi = 0; pi < 2; pi++)
#pragma unroll
                for (int tn = 0; tn < 2; tn++)
#pragma unroll
                    for (int c = 0; c < 4; c++) {
                        float m = tmp[pi][tn][c];
#pragma unroll
                        for (int a = 0; a < 2; a++) {
                            if (AR[a][pr] == 0.f) continue;
#pragma unroll
                            for (int b = 0; b < 2; b++) {
                                if (AR[b][pc] == 0.f) continue;
                                Y[pi][tn][a * 2 + b][c] +=
                                    AR[a][pr] * AR[b][pc] * m;
                            }
                        }
                    }
        }

        // prefetch this warp's slice of U[p+3]
        if (p + 3 < 16) issue_u(p + 3, (p + 3) % 3);
        else cp_commit();
    }

    // ---------------- epilogue: bias + GELU + per-pixel GN + store ----------
    const int ocr = wid * 16 + (l >> 2);
    const float b_lo = __ldg(bias + ocr), b_hi = __ldg(bias + ocr + 8);
    const float w_lo = __ldg(gnw + ocr),  w_hi = __ldg(gnw + ocr + 8);
    const float a_lo = __ldg(gnb + ocr),  a_hi = __ldg(gnb + ocr + 8);

#pragma unroll
    for (int pi = 0; pi < 2; pi++) {
#pragma unroll
        for (int tn = 0; tn < 2; tn++) {
            float g[4][4], o[4][4];
#pragma unroll
            for (int ab = 0; ab < 4; ab++) {
                g[0][ab] = gelu_tanh(Y[pi][tn][ab][0] + b_lo);
                g[1][ab] = gelu_tanh(Y[pi][tn][ab][1] + b_lo);
                g[2][ab] = gelu_tanh(Y[pi][tn][ab][2] + b_hi);
                g[3][ab] = gelu_tanh(Y[pi][tn][ab][3] + b_hi);
            }
#pragma unroll
            for (int u = 0; u < 2; u++)
#pragma unroll
                for (int ab = 0; ab < 4; ab++) {
                    float v0 = g[u][ab], v1 = g[u + 2][ab];
                    float s1 = v0 + v1, s2 = v0 * v0 + v1 * v1;
#pragma unroll
                    for (int m = 4; m <= 16; m <<= 1) {
                        s1 += __shfl_xor_sync(0xffffffffu, s1, m);
                        s2 += __shfl_xor_sync(0xffffffffu, s2, m);
                    }
                    float mean = s1 * (1.0f / 16.0f);
                    float var  = s2 * (1.0f / 16.0f) - mean * mean;
                    float rstd = rsqrtf(var + 1e-5f);
                    o[u][ab]     = (v0 - mean) * rstd * w_lo + a_lo;
                    o[u + 2][ab] = (v1 - mean) * rstd * w_hi + a_hi;
                }
            int colbase = ps * 64 + 32 * pi + 16 * tn + 4 * (l & 3);
#pragma unroll
            for (int rr = 0; rr < 2; rr++) {
                int oc = ocr + rr * 8;
#pragma unroll
                for (int a = 0; a < 2; a++) {
                    float* dst = out + (((size_t)n * COUT + oc) * HH +
                                        (2 * hb + a)) * WW + colbase;
                    *(float4*)dst = make_float4(o[rr * 2 + 0][a * 2 + 0],
                                                o[rr * 2 + 0][a * 2 + 1],
                                                o[rr * 2 + 1][a * 2 + 0],
                                                o[rr * 2 + 1][a * 2 + 1]);
                }
            }
        }
    }
}

extern "C" void kernel_launch(void* const* d_in, const int* in_sizes, int n_in,
                              void* d_out, int out_size) {
    const float* x   = (const float*)d_in[0];
    const float* w   = (const float*)d_in[1];
    const float* b   = (const float*)d_in[2];
    const float* gnw = (const float*)d_in[3];
    const float* gnb = (const float*)d_in[4];
    float* out = (float*)d_out;

    prep_all<<<32 + HH * NB, 256>>>(w, x);

    cudaFuncSetAttribute(convt_wino_kernel,
                         cudaFuncAttributeMaxDynamicSharedMemorySize, SMEM_SZ);
    convt_wino_kernel<<<dim3(HH, NB), 256, SMEM_SZ>>>(b, gnw, gnb, out);
}

// round 16
// speedup vs baseline: 1.5668x; 1.0917x over previous
#include <cuda_runtime.h>
#include <cuda_fp16.h>
#include <math.h>
#include <stdint.h>

#define CIN   64
#define COUT  128
#define HH    128
#define WW    128
#define NB    32

// ---------------- persistent scratch (__device__ globals) -------------------
__device__ uint4 g_x1[(size_t)NB * HH * 1024];   // [n][h][pix(128)][ic(64)] fp16
// U in mma-fragment-linear order: [pos(16)][warp(8)][kc(4)][lane(32)] x uint4
// (corner pos 3,12 sign-folded at prep time)
__device__ uint4 g_uf[16 * 8 * 4 * 32];

// ---------------- fused pre-pass: blocks 0..31 = U, 32..4127 = x ------------
__global__ void prep_all(const float* __restrict__ w,
                         const float* __restrict__ x) {
    __shared__ __half sh[128 * 72];
    const int bid = blockIdx.x;

    if (bid < 32) {
        // ---- Winograd U (fp32-exact -> fp16), scattered to fragment layout --
        int idx = bid * 256 + threadIdx.x;          // 0..8191 = oc*64+ic
        if (idx >= COUT * CIN) return;
        int oc = idx >> 6, ic = idx & 63;
        float g[3][3];
#pragma unroll
        for (int r = 0; r < 3; r++)
#pragma unroll
            for (int c = 0; c < 3; c++)
                g[r][c] = w[((size_t)(ic * COUT + oc) * 3 + (2 - r)) * 3 + (2 - c)];
        float t[4][3];
#pragma unroll
        for (int c = 0; c < 3; c++) {
            t[0][c] = g[0][c];
            t[1][c] = 0.5f * (g[0][c] + g[1][c] + g[2][c]);
            t[2][c] = 0.5f * (g[0][c] - g[1][c] + g[2][c]);
            t[3][c] = g[2][c];
        }
        // fragment scatter coordinates for this (oc, ic)
        const int ws = oc >> 4;
        const int l  = ((oc & 7) << 2) | ((ic & 7) >> 1);
        const int reg = ((oc >> 3) & 1) | (((ic >> 3) & 1) << 1);
        const int kc = ic >> 4;
        const int h  = ic & 1;
        __half* dst = (__half*)g_uf;
#pragma unroll
        for (int r = 0; r < 4; r++) {
            float u[4];
            u[0] = t[r][0];
            u[1] = 0.5f * (t[r][0] + t[r][1] + t[r][2]);
            u[2] = 0.5f * (t[r][0] - t[r][1] + t[r][2]);
            u[3] = t[r][2];
            if (r == 3) u[0] = -u[0];       // pos 12 = (3,0): a-coef -1
            if (r == 0) u[3] = -u[3];       // pos 3  = (0,3): b-coef -1
#pragma unroll
            for (int cc = 0; cc < 4; cc++) {
                int pos = r * 4 + cc;
                size_t hidx = ((((size_t)(pos * 8 + ws) * 4 + kc) * 32 + l) * 4
                               + reg) * 2 + h;
                dst[hidx] = __float2half_rn(u[cc]);
            }
        }
        return;
    }

    // ---- x -> fp16 transposed tiles ----
    const int r2 = bid - 32;
    const int h = r2 & 127, n = r2 >> 7;
    const float* xb = x + (size_t)n * CIN * HH * WW;
#pragma unroll
    for (int i = 0; i < 8; i++) {
        int f = threadIdx.x + i * 256;
        int ic = f >> 5, p4 = f & 31;
        float4 v = *(const float4*)(xb + ((size_t)ic * HH + h) * WW + p4 * 4);
        float vv[4] = {v.x, v.y, v.z, v.w};
#pragma unroll
        for (int j = 0; j < 4; j++)
            sh[(p4 * 4 + j) * 72 + ic] = __float2half_rn(vv[j]);
    }
    __syncthreads();
    uint4* dst = g_x1 + (size_t)(n * HH + h) * 1024;
    for (int q = threadIdx.x; q < 1024; q += 256) {
        int p = q >> 3, c = q & 7;
        dst[q] = *(const uint4*)((const char*)sh + p * 144 + c * 16);
    }
}

// ---------------- main kernel ----------------------------------------------
// CTA = output rows {2hb, 2hb+1} x 64 pixels (32 Winograd tiles).
// smem: V [16 pos][32 tiles][128B swz] = 65536; x stage 34816B at 65536.
#define VPOS_B 4096
#define XOFF   65536
#define SMEM_SZ 100352

static __device__ __forceinline__ unsigned smem_u32(const void* p) {
    unsigned r;
    asm("{ .reg .u64 t; cvta.to.shared.u64 t, %1; cvt.u32.u64 %0, t; }"
        : "=r"(r) : "l"(p));
    return r;
}
__device__ __forceinline__ void cp16(unsigned dst, const void* src, int bytes) {
    asm volatile("cp.async.cg.shared.global [%0], [%1], 16, %2;"
                 :: "r"(dst), "l"(src), "r"(bytes));
}
__device__ __forceinline__ void ldsm4(unsigned r[4], unsigned addr) {
    asm volatile("ldmatrix.sync.aligned.m8n8.x4.shared.b16 {%0,%1,%2,%3}, [%4];"
                 : "=r"(r[0]), "=r"(r[1]), "=r"(r[2]), "=r"(r[3]) : "r"(addr));
}
__device__ __forceinline__ void mma16816(float c[4], unsigned a0, unsigned a1,
                                         unsigned a2, unsigned a3,
                                         unsigned b0, unsigned b1) {
    asm volatile(
        "mma.sync.aligned.m16n8k16.row.col.f32.f16.f16.f32 "
        "{%0,%1,%2,%3}, {%4,%5,%6,%7}, {%8,%9}, {%0,%1,%2,%3};"
        : "+f"(c[0]), "+f"(c[1]), "+f"(c[2]), "+f"(c[3])
        : "r"(a0), "r"(a1), "r"(a2), "r"(a3), "r"(b0), "r"(b1));
}
__device__ __forceinline__ void mma16816_dc(float d[4], unsigned a0, unsigned a1,
                                            unsigned a2, unsigned a3,
                                            unsigned b0, unsigned b1,
                                            const float c[4]) {
    asm volatile(
        "mma.sync.aligned.m16n8k16.row.col.f32.f16.f16.f32 "
        "{%0,%1,%2,%3}, {%4,%5,%6,%7}, {%8,%9}, {%10,%11,%12,%13};"
        : "=f"(d[0]), "=f"(d[1]), "=f"(d[2]), "=f"(d[3])
        : "r"(a0), "r"(a1), "r"(a2), "r"(a3), "r"(b0), "r"(b1),
          "f"(c[0]), "f"(c[1]), "f"(c[2]), "f"(c[3]));
}
__device__ __forceinline__ float gelu_tanh(float y) {
    float u = 1.5957691216f * (y + 0.044715f * y * y * y);
    return __fdividef(y, 1.0f + __expf(-u));
}

extern __shared__ char dyn_smem[];

__global__ __launch_bounds__(256, 2)
void convt_wino_kernel(const float* __restrict__ bias,
                       const float* __restrict__ gnw,
                       const float* __restrict__ gnb,
                       float* __restrict__ out) {
    const int hb = blockIdx.x >> 1;     // output rows {2hb, 2hb+1}
    const int ps = blockIdx.x & 1;      // pixel slice: 64 px at ps*64
    const int n = blockIdx.y;
    const int tid = threadIdx.x;
    const int wid = tid >> 5;
    const int l = tid & 31;

    const unsigned sb = smem_u32(dyn_smem);

    // ---- prologue: x stage (4 rows x 68 lp x 64 ic) ----
    {
#pragma unroll
        for (int k = 0; k < 9; k++) {
            int idx = tid + k * 256;            // need < 2176
            if (idx < 4 * 68 * 8) {
                int c = idx & 7;
                int lp = (idx >> 3) % 68;
                int i = idx / (68 * 8);
                int gh = 2 * hb - 2 + i;
                int gp = ps * 64 - 2 + lp;
                bool ok = (gh >= 0) && (gp >= 0) && (gp < WW);
                const char* src = (const char*)g_x1 +
                    (size_t)(n * HH + (gh < 0 ? 0 : gh)) * 16384 +
                    (ok ? gp : 0) * 128 + c * 16;
                cp16(sb + XOFF + (unsigned)(i * 68 + lp) * 128 + c * 16, src,
                     ok ? 16 : 0);
            }
        }
        asm volatile("cp.async.commit_group;");
        asm volatile("cp.async.wait_group 0;");
        __syncthreads();
    }

    // ---- V transform (fp32 math, fp16 store, swizzled rows) ----------------
#pragma unroll
    for (int jb = 0; jb < 4; jb++) {
        int idx = tid + jb * 256;       // 0..1023
        int tl = idx >> 5, q = idx & 31;
        const unsigned vxr = (unsigned)((tl & 7) << 4);
        float2 d[4][4];
#pragma unroll
        for (int i = 0; i < 4; i++)
#pragma unroll
            for (int jj = 0; jj < 4; jj++) {
                __half2 hv = *(const __half2*)
                    (dyn_smem + XOFF + (i * 68 + 2 * tl + jj) * 128 + q * 4);
                d[i][jj] = __half22float2(hv);
            }
        float2 e[4][4];
#pragma unroll
        for (int jj = 0; jj < 4; jj++) {
            e[0][jj] = make_float2(d[0][jj].x - d[2][jj].x, d[0][jj].y - d[2][jj].y);
            e[1][jj] = make_float2(d[1][jj].x + d[2][jj].x, d[1][jj].y + d[2][jj].y);
            e[2][jj] = make_float2(d[2][jj].x - d[1][jj].x, d[2][jj].y - d[1][jj].y);
            e[3][jj] = make_float2(d[1][jj].x - d[3][jj].x, d[1][jj].y - d[3][jj].y);
        }
#pragma unroll
        for (int r = 0; r < 4; r++) {
            float2 v[4];
            v[0] = make_float2(e[r][0].x - e[r][2].x, e[r][0].y - e[r][2].y);
            v[1] = make_float2(e[r][1].x + e[r][2].x, e[r][1].y + e[r][2].y);
            v[2] = make_float2(e[r][2].x - e[r][1].x, e[r][2].y - e[r][1].y);
            v[3] = make_float2(e[r][1].x - e[r][3].x, e[r][1].y - e[r][3].y);
#pragma unroll
            for (int s = 0; s < 4; s++)
                *(__half2*)(dyn_smem + (r * 4 + s) * VPOS_B + tl * 128 +
                            (unsigned)((q * 4) ^ vxr)) =
                    __floats2half2_rn(v[s].x, v[s].y);
        }
    }
    __syncthreads();                    // LAST barrier in the kernel

    // ---- per-lane ldmatrix components (B from V smem) ----
    const int bRow = (l & 7) + ((l & 16) ? 8 : 0);
    const unsigned bXr = (unsigned)((bRow & 7) << 4);
    const unsigned bKoff = (l & 8) ? 16u : 0u;

    // A fragment gmem pointer for this (warp, lane)
    const uint4* Abase = g_uf + (size_t)wid * 4 * 32 + l;

    // ---- Y accumulators: [pi][tn][ab][c] ----
    float Y[2][2][4][4];
#pragma unroll
    for (int pi = 0; pi < 2; pi++)
#pragma unroll
        for (int tn = 0; tn < 2; tn++)
#pragma unroll
            for (int ab = 0; ab < 4; ab++)
#pragma unroll
                for (int c = 0; c < 4; c++) Y[pi][tn][ab][c] = 0.f;

    float zero4[4] = {0.f, 0.f, 0.f, 0.f};
    constexpr float AR[2][4] = {{1.f, 1.f, 1.f, 0.f}, {0.f, 1.f, -1.f, -1.f}};

    // ---- mainloop over 16 Winograd positions (A via LDG, no barriers) ------
#pragma unroll
    for (int p = 0; p < 16; p++) {
        const int pr = p >> 2, pc = p & 3;
        const bool corner = (pr == 0 || pr == 3) && (pc == 0 || pc == 3);
        const int cab = (pr ? 2 : 0) + (pc ? 1 : 0);
        const unsigned vb0 = sb + (unsigned)p * VPOS_B + (unsigned)bRow * 128;
        const unsigned vb1 = vb0 + 2048;

        // batched A-fragment loads for this pos (4 x LDG.128, MLP=4)
        uint4 av[4];
#pragma unroll
        for (int kc = 0; kc < 4; kc++)
            av[kc] = __ldg(Abase + (size_t)(p * 8) * 4 * 32 + kc * 32);

        if (corner) {
#pragma unroll
            for (int kc = 0; kc < 4; kc++) {
                unsigned b0[4], b1[4];
                const unsigned csw = ((unsigned)(kc * 32) + bKoff) ^ bXr;
                ldsm4(b0, vb0 + csw);
                ldsm4(b1, vb1 + csw);
                mma16816(Y[0][0][cab], av[kc].x, av[kc].y, av[kc].z, av[kc].w,
                         b0[0], b0[1]);
                mma16816(Y[0][1][cab], av[kc].x, av[kc].y, av[kc].z, av[kc].w,
                         b0[2], b0[3]);
                mma16816(Y[1][0][cab], av[kc].x, av[kc].y, av[kc].z, av[kc].w,
                         b1[0], b1[1]);
                mma16816(Y[1][1][cab], av[kc].x, av[kc].y, av[kc].z, av[kc].w,
                         b1[2], b1[3]);
            }
        } else {
            float tmp[2][2][4];
#pragma unroll
            for (int kc = 0; kc < 4; kc++) {
                unsigned b0[4], b1[4];
                const unsigned csw = ((unsigned)(kc * 32) + bKoff) ^ bXr;
                ldsm4(b0, vb0 + csw);
                ldsm4(b1, vb1 + csw);
                if (kc == 0) {
                    mma16816_dc(tmp[0][0], av[0].x, av[0].y, av[0].z, av[0].w,
                                b0[0], b0[1], zero4);
                    mma16816_dc(tmp[0][1], av[0].x, av[0].y, av[0].z, av[0].w,
                                b0[2], b0[3], zero4);
                    mma16816_dc(tmp[1][0], av[0].x, av[0].y, av[0].z, av[0].w,
                                b1[0], b1[1], zero4);
                    mma16816_dc(tmp[1][1], av[0].x, av[0].y, av[0].z, av[0].w,
                                b1[2], b1[3], zero4);
                } else {
                    mma16816(tmp[0][0], av[kc].x, av[kc].y, av[kc].z, av[kc].w,
                             b0[0], b0[1]);
                    mma16816(tmp[0][1], av[kc].x, av[kc].y, av[kc].z, av[kc].w,
                             b0[2], b0[3]);
                    mma16816(tmp[1][0], av[kc].x, av[kc].y, av[kc].z, av[kc].w,
                             b1[0], b1[1]);
                    mma16816(tmp[1][1], av[kc].x, av[kc].y, av[kc].z, av[kc].w,
                             b1[2], b1[3]);
                }
            }
            // fold inverse transform (coefs 0/+-1, compile-time pruned)
#pragma unroll
            for (int pi = 0; pi < 2; pi++)
#pragma unroll
                for (int tn = 0; tn < 2; tn++)
#pragma unroll
                    for (int c = 0; c < 4; c++) {
                        float m = tmp[pi][tn][c];
#pragma unroll
                        for (int a = 0; a < 2; a++) {
                            if (AR[a][pr] == 0.f) continue;
#pragma unroll
                            for (int b = 0; b < 2; b++) {
                                if (AR[b][pc] == 0.f) continue;
                                Y[pi][tn][a * 2 + b][c] +=
                                    AR[a][pr] * AR[b][pc] * m;
                            }
                        }
                    }
        }
    }

    // ---------------- epilogue: bias + GELU + per-pixel GN + store ----------
    const int ocr = wid * 16 + (l >> 2);
    const float b_lo = __ldg(bias + ocr), b_hi = __ldg(bias + ocr + 8);
    const float w_lo = __ldg(gnw + ocr),  w_hi = __ldg(gnw + ocr + 8);
    const float a_lo = __ldg(gnb + ocr),  a_hi = __ldg(gnb + ocr + 8);

#pragma unroll
    for (int pi = 0; pi < 2; pi++) {
#pragma unroll
        for (int tn = 0; tn < 2; tn++) {
            float g[4][4], o[4][4];
#pragma unroll
            for (int ab = 0; ab < 4; ab++) {
                g[0][ab] = gelu_tanh(Y[pi][tn][ab][0] + b_lo);
                g[1][ab] = gelu_tanh(Y[pi][tn][ab][1] + b_lo);
                g[2][ab] = gelu_tanh(Y[pi][tn][ab][2] + b_hi);
                g[3][ab] = gelu_tanh(Y[pi][tn][ab][3] + b_hi);
            }
#pragma unroll
            for (int u = 0; u < 2; u++)
#pragma unroll
                for (int ab = 0; ab < 4; ab++) {
                    float v0 = g[u][ab], v1 = g[u + 2][ab];
                    float s1 = v0 + v1, s2 = v0 * v0 + v1 * v1;
#pragma unroll
                    for (int m = 4; m <= 16; m <<= 1) {
                        s1 += __shfl_xor_sync(0xffffffffu, s1, m);
                        s2 += __shfl_xor_sync(0xffffffffu, s2, m);
                    }
                    float mean = s1 * (1.0f / 16.0f);
                    float var  = s2 * (1.0f / 16.0f) - mean * mean;
                    float rstd = rsqrtf(var + 1e-5f);
                    o[u][ab]     = (v0 - mean) * rstd * w_lo + a_lo;
                    o[u + 2][ab] = (v1 - mean) * rstd * w_hi + a_hi;
                }
            int colbase = ps * 64 + 32 * pi + 16 * tn + 4 * (l & 3);
#pragma unroll
            for (int rr = 0; rr < 2; rr++) {
                int oc = ocr + rr * 8;
#pragma unroll
                for (int a = 0; a < 2; a++) {
                    float* dst = out + (((size_t)n * COUT + oc) * HH +
                                        (2 * hb + a)) * WW + colbase;
                    *(float4*)dst = make_float4(o[rr * 2 + 0][a * 2 + 0],
                                                o[rr * 2 + 0][a * 2 + 1],
                                                o[rr * 2 + 1][a * 2 + 0],
                                                o[rr * 2 + 1][a * 2 + 1]);
                }
            }
        }
    }
}

extern "C" void kernel_launch(void* const* d_in, const int* in_sizes, int n_in,
                              void* d_out, int out_size) {
    const float* x   = (const float*)d_in[0];
    const float* w   = (const float*)d_in[1];
    const float* b   = (const float*)d_in[2];
    const float* gnw = (const float*)d_in[3];
    const float* gnb = (const float*)d_in[4];
    float* out = (float*)d_out;

    prep_all<<<32 + HH * NB, 256>>>(w, x);

    cudaFuncSetAttribute(convt_wino_kernel,
                         cudaFuncAttributeMaxDynamicSharedMemorySize, SMEM_SZ);
    convt_wino_kernel<<<dim3(HH, NB), 256, SMEM_SZ>>>(b, gnw, gnb, out);
}